// round 16
// baseline (speedup 1.0000x reference)
#include <cuda_runtime.h>
#include <cuda_fp16.h>
#include <math.h>
#include <stdint.h>

#define BB 64
#define TT 512
#define VV 256
#define MEM 1024
#define G4 4096

// ---------------- device scratch ----------------
__device__ float g_Zx[(size_t)TT * BB * G4];            // layer0 input-side z (+b0), gate-permuted cols, fp32
__device__ float g_hall[(size_t)TT * BB * MEM];         // h1 sequence fp32 (phase-5 input)
__device__ float g_c[2][BB * MEM];                      // cell state per layer, fp32
__device__ uint32_t g_h0[2][BB * 512];                  // h0 packed half2, double-buffered by round parity
__device__ uint32_t g_h1[2][BB * 512];                  // h1 packed half2
__device__ float g_hfin[2][BB * MEM];                   // final-step h, fp32
__device__ uint32_t g_W0h[((VV + MEM) / 2) * G4];       // W0 packed half2 pairs along k, gate-permuted cols
__device__ uint32_t g_W1h[((2 * MEM) / 2) * G4];        // W1 same
__device__ __half g_W0t[(size_t)G4 * (VV + MEM)];       // W0^T [n][k] halves, gate-permuted n (phase1 B)
__device__ __half g_W1t[(size_t)G4 * (2 * MEM)];        // W1^T [n][k] (streamed W1x source, u32 view)
__device__ __half g_Wot[(size_t)VV * MEM];              // W_out^T [n][k] halves
__device__ float g_b0p[G4];
__device__ float g_b1p[G4];
__device__ volatile int g_arrive[128];                  // grid-barrier flags

__device__ __forceinline__ float sigm(float x) { return 1.0f / (1.0f + expf(-x)); }
__device__ __forceinline__ uint32_t pk(float a, float b) {
    __half2 h = __floats2half2_rn(a, b);
    return *(uint32_t*)&h;
}
__device__ __forceinline__ uint32_t smem_u32(const void* p) {
    uint32_t a;
    asm("{ .reg .u64 t; cvta.to.shared.u64 t, %1; cvt.u32.u64 %0, t; }" : "=r"(a) : "l"(p));
    return a;
}
__device__ __forceinline__ void cpa16(uint32_t dst, const void* src) {
    asm volatile("cp.async.cg.shared.global [%0], [%1], 16;" :: "r"(dst), "l"(src));
}
__device__ __forceinline__ void cpa_commit() { asm volatile("cp.async.commit_group;" ::: "memory"); }
#define WAITG(n) asm volatile("cp.async.wait_group %0;" :: "n"(n) : "memory")

// m16n8k16 fp16 mma, fp32 accum
__device__ __forceinline__ void mma16(float* d, uint32_t a0, uint32_t a1, uint32_t a2, uint32_t a3,
                                      uint32_t b0, uint32_t b1) {
    asm volatile("mma.sync.aligned.m16n8k16.row.col.f32.f16.f16.f32 "
                 "{%0,%1,%2,%3}, {%4,%5,%6,%7}, {%8,%9}, {%0,%1,%2,%3};"
                 : "+f"(d[0]), "+f"(d[1]), "+f"(d[2]), "+f"(d[3])
                 : "r"(a0), "r"(a1), "r"(a2), "r"(a3), "r"(b0), "r"(b1));
}

// ---------------- init ----------------
__global__ void init_state(const float* __restrict__ s0, const float* __restrict__ s1) {
    int i = blockIdx.x * 256 + threadIdx.x;
    int b = i >> 10, u = i & 1023;
    g_c[0][i] = s0[b * 2 * MEM + u];
    g_c[1][i] = s1[b * 2 * MEM + u];
    if (u < 512) {
        int kp = u;
        g_h0[1][b * 512 + kp] = pk(s0[b * 2 * MEM + MEM + 2 * kp], s0[b * 2 * MEM + MEM + 2 * kp + 1]);
        g_h1[1][b * 512 + kp] = pk(s1[b * 2 * MEM + MEM + 2 * kp], s1[b * 2 * MEM + MEM + 2 * kp + 1]);
    }
    if (blockIdx.x == 0 && threadIdx.x < 128) g_arrive[threadIdx.x] = 0;
}

// ---------------- gate-permuted packed-half2 K-major weights + fp32 permuted biases ----------------
__global__ void permute_w(const float* __restrict__ W0, const float* __restrict__ b0,
                          const float* __restrict__ W1, const float* __restrict__ b1) {
    size_t i = (size_t)blockIdx.x * 256 + threadIdx.x;
    const size_t n0 = (size_t)((VV + MEM) / 2) * MEM;
    const size_t n1 = (size_t)((2 * MEM) / 2) * MEM;
    if (i < n0) {
        size_t kp = i >> 10; int u = (int)(i & 1023);
        const float* s = W0 + (size_t)(2 * kp) * G4 + u;
        uint4 v;
        v.x = pk(s[0],    s[G4]);
        v.y = pk(s[1024], s[G4 + 1024]);
        v.z = pk(s[2048], s[G4 + 2048]);
        v.w = pk(s[3072], s[G4 + 3072]);
        *(uint4*)&g_W0h[kp * G4 + (size_t)u * 4] = v;
    } else if (i < n0 + n1) {
        size_t k = i - n0;
        size_t kp = k >> 10; int u = (int)(k & 1023);
        const float* s = W1 + (size_t)(2 * kp) * G4 + u;
        uint4 v;
        v.x = pk(s[0],    s[G4]);
        v.y = pk(s[1024], s[G4 + 1024]);
        v.z = pk(s[2048], s[G4 + 2048]);
        v.w = pk(s[3072], s[G4 + 3072]);
        *(uint4*)&g_W1h[kp * G4 + (size_t)u * 4] = v;
    }
    if (i < MEM) {
        int u = (int)i;
        float4 vb0 = { b0[u], b0[1024 + u], b0[2048 + u], b0[3072 + u] };
        float4 vb1 = { b1[u], b1[1024 + u], b1[2048 + u], b1[3072 + u] };
        *(float4*)&g_b0p[u * 4] = vb0;
        *(float4*)&g_b1p[u * 4] = vb1;
    }
}

// ---------------- transposed half weights WT[n][k] (gate-permuted n) ----------------
__global__ __launch_bounds__(256) void transpose_w2(const float* __restrict__ W, int sel) {
    __shared__ float s[32][33];
    int tx = threadIdx.x & 31, ty = threadIdx.x >> 5;
    int k0 = blockIdx.x * 32, c0 = blockIdx.y * 32;
    __half* dst = (sel == 0) ? g_W0t : g_W1t;
    long wst = (sel == 0) ? (VV + MEM) : (2 * MEM);
#pragma unroll
    for (int j = 0; j < 4; j++)
        s[ty + j * 8][tx] = W[(size_t)(k0 + ty + j * 8) * G4 + c0 + tx];
    __syncthreads();
#pragma unroll
    for (int j = 0; j < 4; j++) {
        int c = c0 + ty + j * 8;
        int n = (c & 1023) * 4 + (c >> 10);
        dst[(size_t)n * wst + k0 + tx] = __float2half_rn(s[tx][ty + j * 8]);
    }
}

__global__ __launch_bounds__(256) void transpose_wout(const float* __restrict__ W) {
    __shared__ float s[32][33];
    int tx = threadIdx.x & 31, ty = threadIdx.x >> 5;
    int k0 = blockIdx.x * 32, c0 = blockIdx.y * 32;
#pragma unroll
    for (int j = 0; j < 4; j++)
        s[ty + j * 8][tx] = W[(size_t)(k0 + ty + j * 8) * VV + c0 + tx];
    __syncthreads();
#pragma unroll
    for (int j = 0; j < 4; j++) {
        int n = c0 + ty + j * 8;
        g_Wot[(size_t)n * MEM + k0 + tx] = __float2half_rn(s[tx][ty + j * 8]);
    }
}

// ---------------- fp16 mma GEMM (phases 1/5), unchanged ----------------
__global__ __launch_bounds__(256) void gemm_mma(
    const float* __restrict__ Ain, long sb, long st,
    long wst, int K, int src_gh, int w_sel,
    float* __restrict__ Cout, const float* __restrict__ bias_ext,
    long ocb, long oct)
{
    const float* A = src_gh ? (const float*)g_hall : Ain;
    const __half* WT = (w_sel == 0) ? g_W0t : ((w_sel == 1) ? g_W1t : g_Wot);
    const float* bias = (w_sel == 0) ? g_b0p : ((w_sel == 1) ? g_b1p : bias_ext);
    float* C = (w_sel == 2) ? Cout : (float*)g_Zx;

    __shared__ uint32_t As[128 * 32];
    __shared__ uint32_t Bs[64 * 32];

    const int tid = threadIdx.x;
    const int wid = tid >> 5, lane = tid & 31;
    const int gid = lane >> 2, tig = lane & 3;
    const int wm = wid & 3, wn = wid >> 2;
    const long brow = (long)blockIdx.y * 128;
    const int bcol = blockIdx.x * 64;

    int a_sw[4];
    const float* a_ptr[4];
#pragma unroll
    for (int i = 0; i < 4; i++) {
        int f = tid + i * 256;
        int row = f >> 3, g4 = f & 7;
        a_sw[i] = row * 32 + ((g4 * 4) ^ ((row & 7) * 4));
        long r = brow + row;
        a_ptr[i] = A + (r & 63) * sb + (r >> 6) * st + g4 * 8;
    }
    int b_sw[2];
    const uint32_t* b_ptr[2];
#pragma unroll
    for (int i = 0; i < 2; i++) {
        int f = tid + i * 256;
        int n = f >> 3, g4 = f & 7;
        b_sw[i] = n * 32 + ((g4 * 4) ^ ((n & 7) * 4));
        b_ptr[i] = (const uint32_t*)(WT + (size_t)(bcol + n) * wst) + g4 * 4;
    }

    float acc[2][4][4];
#pragma unroll
    for (int mt = 0; mt < 2; mt++)
#pragma unroll
        for (int nt = 0; nt < 4; nt++)
#pragma unroll
            for (int q = 0; q < 4; q++) acc[mt][nt][q] = 0.0f;

    const int arow0 = wm * 32 + gid;
    const int nb0 = wn * 32 + gid;
    const int xg = gid * 4;

    for (int kb = 0; kb < K; kb += 64) {
        float4 alo[4], ahi[4];
        uint4 bv[2];
#pragma unroll
        for (int i = 0; i < 4; i++) {
            alo[i] = *(const float4*)(a_ptr[i] + kb);
            ahi[i] = *(const float4*)(a_ptr[i] + kb + 4);
        }
#pragma unroll
        for (int i = 0; i < 2; i++) bv[i] = *(const uint4*)(b_ptr[i] + kb / 2);
        __syncthreads();
#pragma unroll
        for (int i = 0; i < 4; i++) {
            uint4 v;
            v.x = pk(alo[i].x, alo[i].y);
            v.y = pk(alo[i].z, alo[i].w);
            v.z = pk(ahi[i].x, ahi[i].y);
            v.w = pk(ahi[i].z, ahi[i].w);
            *(uint4*)&As[a_sw[i]] = v;
        }
#pragma unroll
        for (int i = 0; i < 2; i++) *(uint4*)&Bs[b_sw[i]] = bv[i];
        __syncthreads();

#pragma unroll
        for (int ks = 0; ks < 4; ks++) {
            int p0 = (ks * 8 + tig) ^ xg;
            int p1 = (ks * 8 + tig + 4) ^ xg;
            uint32_t a[2][4];
#pragma unroll
            for (int mt = 0; mt < 2; mt++) {
                int r0 = (arow0 + mt * 16) * 32;
                a[mt][0] = As[r0 + p0];
                a[mt][1] = As[r0 + 256 + p0];
                a[mt][2] = As[r0 + p1];
                a[mt][3] = As[r0 + 256 + p1];
            }
#pragma unroll
            for (int nt = 0; nt < 4; nt++) {
                int n = (nb0 + nt * 8) * 32;
                uint32_t b0 = Bs[n + p0];
                uint32_t b1 = Bs[n + p1];
#pragma unroll
                for (int mt = 0; mt < 2; mt++)
                    mma16(acc[mt][nt], a[mt][0], a[mt][1], a[mt][2], a[mt][3], b0, b1);
            }
        }
        __syncthreads();
    }

#pragma unroll
    for (int mt = 0; mt < 2; mt++) {
        long r2 = brow + wm * 32 + mt * 16 + gid;
        long co0 = (r2 & 63) * ocb + (r2 >> 6) * oct;
        long r3 = r2 + 8;
        long co1 = (r3 & 63) * ocb + (r3 >> 6) * oct;
#pragma unroll
        for (int nt = 0; nt < 4; nt++) {
            int col = bcol + wn * 32 + nt * 8 + tig * 2;
            float bz0 = bias[col], bz1 = bias[col + 1];
            float2 v0 = { acc[mt][nt][0] + bz0, acc[mt][nt][1] + bz1 };
            float2 v1 = { acc[mt][nt][2] + bz0, acc[mt][nt][3] + bz1 };
            *(float2*)(C + co0 + col) = v0;
            *(float2*)(C + co1 + col) = v1;
        }
    }
}

// ---------------- fused two-layer persistent recurrence: 513 rounds, 512 threads ----------------
// 16 units of 64-kp chunks (8 h0+W1x, 8 h1), 3-buffer pipeline, issue-after-sync.
// smem: W0h [0,64K) | W1h [64K,128K) | Hbuf 3x16K [128K,176K) | Wbuf 3x8K [176K,200K) | Zx 9216 [200K,..)
// Zs (36864) aliases Hbuf.
#define SMB_W1   65536
#define SMB_HBUF 131072
#define SMB_WBUF 180224
#define SMB_ZX   204800
#define SMB_TOT2 214016

__global__ __launch_bounds__(512) void lstm_fused()
{
    extern __shared__ char dynraw[];
    uint32_t* W0_s = (uint32_t*)dynraw;                    // [32n][512kp^swz]
    uint32_t* W1_s = (uint32_t*)(dynraw + SMB_W1);
    uint32_t* Hb = (uint32_t*)(dynraw + SMB_HBUF);         // 3 x 4096 u32 ([64row][64kp^swz])
    uint32_t* Wb = (uint32_t*)(dynraw + SMB_WBUF);         // 3 x 2048 u32 ([32n][64kp^swz])
    float* Zs  = (float*)(dynraw + SMB_HBUF);              // alias, used post-mainloop: [q4][64][36]
    float* Zx_s = (float*)(dynraw + SMB_ZX);               // [64][36]

    const int bid = blockIdx.x;
    const int tid = threadIdx.x;
    const int n0 = bid * 32;

    const int wid = tid >> 5, lane = tid & 31;
    const int gid = lane >> 2, tig = lane & 3;
    const int kq = wid & 3;            // k quarter (128 kp)
    const int wm = (wid >> 2) & 1;     // m half (32 rows)
    const int wn = wid >> 3;           // n half (16 cols)
    const int xg = gid * 4;

    // preload resident W slices (h-parts), swizzled
    {
        const uint32_t* Wh0 = g_W0h + (size_t)(VV / 2) * G4;
        const uint32_t* Wh1 = g_W1h + (size_t)(MEM / 2) * G4;
        for (int idx = tid; idx < 32 * 512; idx += 512) {
            int kp = idx >> 5, n = idx & 31;
            int d = n * 512 + (kp ^ ((n & 7) * 4));
            W0_s[d] = Wh0[(size_t)kp * G4 + n0 + n];
            W1_s[d] = Wh1[(size_t)kp * G4 + n0 + n];
        }
    }

    const uint32_t sbase = smem_u32(dynraw);

    // h-chunk staging granules (i<2): g = i*512 + tid: q=g>>8, row=(g>>2)&63, k4=g&3
    uint32_t h_dst[2]; int h_soff[2];
#pragma unroll
    for (int i = 0; i < 2; i++) {
        int g = i * 512 + tid;
        int q = g >> 8, row = (g >> 2) & 63, k4 = g & 3;
        h_dst[i] = sbase + (uint32_t)SMB_HBUF
                 + (uint32_t)(row * 64 + ((q * 16 + k4 * 4) ^ ((row & 7) * 4))) * 4u;
        h_soff[i] = row * 512 + q * 128 + k4 * 4;   // + u*16 per chunk
    }
    // W1x chunk staging (1 granule/thread): n=tid&31, q=(tid>>5)&3, k4=(tid>>7)&3
    uint32_t w_dst; size_t w_soff;
    {
        int n = tid & 31, q = (tid >> 5) & 3, k4 = (tid >> 7) & 3;
        w_dst = sbase + (uint32_t)SMB_WBUF
              + (uint32_t)(n * 64 + ((q * 16 + k4 * 4) ^ ((n & 7) * 4))) * 4u;
        w_soff = (size_t)(n0 + n) * 1024 + q * 128 + k4 * 4;   // u32 units, + u*16 per chunk
    }
    const uint32_t* w1x_src = (const uint32_t*)g_W1t;

    // Zx staging (1 granule/thread): m=tid>>3, c4=tid&7
    uint32_t zx_dst; int zx_soff;
    {
        int m = tid >> 3, c4 = tid & 7;
        zx_dst = sbase + (uint32_t)SMB_ZX + (uint32_t)(m * 36 + c4 * 4) * 4u;
        zx_soff = m * G4 + n0 + c4 * 4;
    }

    // fragment constants
    int a_base[2];
#pragma unroll
    for (int mt = 0; mt < 2; mt++)
        a_base[mt] = (wm * 32 + mt * 16 + gid) * 64;
    int b_nidx[2], bc_nidx[2];
#pragma unroll
    for (int nt = 0; nt < 2; nt++) {
        int n = wn * 16 + nt * 8 + gid;
        b_nidx[nt] = n * 512;
        bc_nidx[nt] = n * 64;
    }

    // pointwise constants + c registers (1 elem/thread)
    const int pm = tid >> 3, pj = tid & 7;
    const int ci = pm * MEM + bid * 8 + pj;
    float c0r = g_c[0][ci];
    float c1r = g_c[1][ci];

    // Zx[0] prefetch
    cpa16(zx_dst, g_Zx + zx_soff);
    cpa_commit();
    __syncthreads();   // resident W ready

    for (int r = 0; r <= TT; r++) {
        const int rp = r & 1;
        const uint32_t* h0r = g_h0[1 - rp];     // h0_{r-1}
        const uint32_t* h1r = g_h1[rp];         // h1_{r-2}
        __half* h0w = (__half*)g_h0[rp];
        __half* h1w = (__half*)g_h1[1 - rp];

        // unit u: u<8 -> h0 chunk u + W1x chunk u; u>=8 -> h1 chunk u-8
        auto issue = [&](int u) {
            uint32_t hb = (uint32_t)(u % 3) * 16384u;
            if (u < 8) {
#pragma unroll
                for (int i = 0; i < 2; i++) cpa16(h_dst[i] + hb, h0r + h_soff[i] + u * 16);
                cpa16(w_dst + (uint32_t)(u % 3) * 8192u, w1x_src + w_soff + u * 16);
            } else {
                int j = u - 8;
#pragma unroll
                for (int i = 0; i < 2; i++) cpa16(h_dst[i] + hb, h1r + h_soff[i] + j * 16);
            }
        };

        issue(0); cpa_commit();
        issue(1); cpa_commit();

        float accL0[2][2][4], accL1[2][2][4];
#pragma unroll
        for (int mt = 0; mt < 2; mt++)
#pragma unroll
            for (int nt = 0; nt < 2; nt++)
#pragma unroll
                for (int q = 0; q < 4; q++) { accL0[mt][nt][q] = 0.0f; accL1[mt][nt][q] = 0.0f; }

        for (int u = 0; u < 16; u++) {
            if (u < 15) { WAITG(1); } else { WAITG(0); }
            __syncthreads();
            if (u < 14) { issue(u + 2); cpa_commit(); }

            const uint32_t* Ab = Hb + (u % 3) * 4096;
            if (u < 8) {
                const uint32_t* Wc = Wb + (u % 3) * 2048;
#pragma unroll
                for (int kk = 0; kk < 2; kk++) {
                    int x = kq * 16 + kk * 8 + tig;
                    int p0 = x ^ xg, p1 = (x + 4) ^ xg;
                    uint32_t a[2][4];
#pragma unroll
                    for (int mt = 0; mt < 2; mt++) {
                        a[mt][0] = Ab[a_base[mt] + p0];
                        a[mt][1] = Ab[a_base[mt] + 512 + p0];
                        a[mt][2] = Ab[a_base[mt] + p1];
                        a[mt][3] = Ab[a_base[mt] + 512 + p1];
                    }
                    int kp0 = kq * 128 + u * 16 + kk * 8 + tig;
#pragma unroll
                    for (int nt = 0; nt < 2; nt++) {
                        uint32_t b0 = W0_s[b_nidx[nt] + (kp0 ^ xg)];
                        uint32_t b1 = W0_s[b_nidx[nt] + ((kp0 + 4) ^ xg)];
                        uint32_t c0 = Wc[bc_nidx[nt] + p0];
                        uint32_t c1 = Wc[bc_nidx[nt] + p1];
#pragma unroll
                        for (int mt = 0; mt < 2; mt++) {
                            mma16(accL0[mt][nt], a[mt][0], a[mt][1], a[mt][2], a[mt][3], b0, b1);
                            mma16(accL1[mt][nt], a[mt][0], a[mt][1], a[mt][2], a[mt][3], c0, c1);
                        }
                    }
                }
            } else {
                int j = u - 8;
#pragma unroll
                for (int kk = 0; kk < 2; kk++) {
                    int x = kq * 16 + kk * 8 + tig;
                    int p0 = x ^ xg, p1 = (x + 4) ^ xg;
                    uint32_t a[2][4];
#pragma unroll
                    for (int mt = 0; mt < 2; mt++) {
                        a[mt][0] = Ab[a_base[mt] + p0];
                        a[mt][1] = Ab[a_base[mt] + 512 + p0];
                        a[mt][2] = Ab[a_base[mt] + p1];
                        a[mt][3] = Ab[a_base[mt] + 512 + p1];
                    }
                    int kp0 = kq * 128 + j * 16 + kk * 8 + tig;
#pragma unroll
                    for (int nt = 0; nt < 2; nt++) {
                        uint32_t b0 = W1_s[b_nidx[nt] + (kp0 ^ xg)];
                        uint32_t b1 = W1_s[b_nidx[nt] + ((kp0 + 4) ^ xg)];
#pragma unroll
                        for (int mt = 0; mt < 2; mt++)
                            mma16(accL1[mt][nt], a[mt][0], a[mt][1], a[mt][2], a[mt][3], b0, b1);
                    }
                }
            }
        }
        __syncthreads();   // all Hb/Wb reads done; Zs alias now safe

        // ---- layer0 pointwise (step r), skipped at r == TT ----
        if (r < TT) {
#pragma unroll
            for (int mt = 0; mt < 2; mt++) {
                int row = wm * 32 + mt * 16 + gid;
#pragma unroll
                for (int nt = 0; nt < 2; nt++) {
                    int col = wn * 16 + nt * 8 + tig * 2;
                    *(float2*)&Zs[kq * 2304 + row * 36 + col] =
                        make_float2(accL0[mt][nt][0], accL0[mt][nt][1]);
                    *(float2*)&Zs[kq * 2304 + (row + 8) * 36 + col] =
                        make_float2(accL0[mt][nt][2], accL0[mt][nt][3]);
                }
            }
            __syncthreads();
            {
                float4 z = *(const float4*)&Zx_s[pm * 36 + pj * 4];
#pragma unroll
                for (int q = 0; q < 4; q++) {
                    float4 p = *(const float4*)&Zs[q * 2304 + pm * 36 + pj * 4];
                    z.x += p.x; z.y += p.y; z.z += p.z; z.w += p.w;
                }
                float cn = c0r * sigm(z.z + 1.0f) + sigm(z.x) * tanhf(z.y);
                float hn = tanhf(cn) * sigm(z.w);
                c0r = cn;
                h0w[pm * MEM + bid * 8 + pj] = __float2half_rn(hn);
                if (r == TT - 1) g_hfin[0][ci] = hn;
            }
            __syncthreads();   // Zs reuse
        }

        // ---- layer1 pointwise (step r-1), skipped at r == 0 ----
        if (r >= 1) {
            const int t1 = r - 1;
#pragma unroll
            for (int mt = 0; mt < 2; mt++) {
                int row = wm * 32 + mt * 16 + gid;
#pragma unroll
                for (int nt = 0; nt < 2; nt++) {
                    int col = wn * 16 + nt * 8 + tig * 2;
                    *(float2*)&Zs[kq * 2304 + row * 36 + col] =
                        make_float2(accL1[mt][nt][0], accL1[mt][nt][1]);
                    *(float2*)&Zs[kq * 2304 + (row + 8) * 36 + col] =
                        make_float2(accL1[mt][nt][2], accL1[mt][nt][3]);
                }
            }
            __syncthreads();
            {
                float4 z = *(const float4*)&g_b1p[n0 + pj * 4];
#pragma unroll
                for (int q = 0; q < 4; q++) {
                    float4 p = *(const float4*)&Zs[q * 2304 + pm * 36 + pj * 4];
                    z.x += p.x; z.y += p.y; z.z += p.z; z.w += p.w;
                }
                float cn = c1r * sigm(z.z + 1.0f) + sigm(z.x) * tanhf(z.y);
                float hn = tanhf(cn) * sigm(z.w);
                c1r = cn;
                h1w[pm * MEM + bid * 8 + pj] = __float2half_rn(hn);
                g_hall[(size_t)t1 * BB * MEM + ci] = hn;
                if (t1 == TT - 1) g_hfin[1][ci] = hn;
            }
        }

        // ---- publish + barrier ----
        if (r < TT) {
            __threadfence();
            __syncthreads();
            int want = r + 1;
            if (tid == 0) g_arrive[bid] = want;

            if (r + 1 < TT) {
                cpa16(zx_dst, g_Zx + (size_t)(r + 1) * BB * G4 + zx_soff);
                cpa_commit();
            }

            if (tid < 128) {
                while (g_arrive[tid] < want) { }
            }
            __syncthreads();
        }
    }

    g_c[0][ci] = c0r;
    g_c[1][ci] = c1r;
}

// ---------------- pack final_state [2, B, 2*MEM] ----------------
__global__ void state_pack(float* __restrict__ out)
{
    int i = blockIdx.x * 256 + threadIdx.x;
    int l = i / (BB * 2 * MEM);
    int rem = i % (BB * 2 * MEM);
    int b = rem / (2 * MEM);
    int u = rem % (2 * MEM);
    out[i] = (u < MEM) ? g_c[l][b * MEM + u] : g_hfin[l][b * MEM + (u - MEM)];
}

extern "C" void kernel_launch(void* const* d_in, const int* in_sizes, int n_in,
                              void* d_out, int out_size)
{
    const float* x    = (const float*)d_in[0];
    const float* s0   = (const float*)d_in[1];
    const float* s1   = (const float*)d_in[2];
    const float* W0   = (const float*)d_in[3];
    const float* b0   = (const float*)d_in[4];
    const float* W1   = (const float*)d_in[5];
    const float* b1   = (const float*)d_in[6];
    const float* Wout = (const float*)d_in[7];
    const float* bout = (const float*)d_in[8];
    float* out = (float*)d_out;

    cudaFuncSetAttribute(lstm_fused,
                         cudaFuncAttributeMaxDynamicSharedMemorySize, SMB_TOT2);

    init_state<<<256, 256>>>(s0, s1);

    {
        size_t total = (size_t)((VV + MEM) / 2) * MEM + (size_t)MEM * MEM;
        int blocks = (int)((total + 255) / 256);
        permute_w<<<blocks, 256>>>(W0, b0, W1, b1);
    }
    transpose_w2<<<dim3((VV + MEM) / 32, G4 / 32), 256>>>(W0, 0);
    transpose_w2<<<dim3((2 * MEM) / 32, G4 / 32), 256>>>(W1, 1);
    transpose_wout<<<dim3(MEM / 32, VV / 32), 256>>>(Wout);

    // Phase 1: Zx = x @ W0[:256,:] + b0   (M=32768, N=4096, K=256)
    gemm_mma<<<dim3(64, 256), 256>>>(x, (long)TT * VV, (long)VV,
                                     (long)(VV + MEM), VV, 0, 0,
                                     nullptr, nullptr, (long)G4, (long)BB * G4);

    // Fused two-layer recurrence: 513 rounds, one launch, 512 threads/block
    lstm_fused<<<128, 512, SMB_TOT2>>>();

    // Phase 5: out[b,t,:] = h1_all @ W_out + b_out   (M=32768, N=256, K=1024)
    gemm_mma<<<dim3(4, 256), 256>>>(nullptr, (long)MEM, (long)BB * MEM,
                                    (long)MEM, MEM, 1, 2,
                                    out, bout, (long)TT * VV, (long)VV);

    state_pack<<<1024, 256>>>(out + (size_t)BB * TT * VV);
}

// round 17
// speedup vs baseline: 1.1252x; 1.1252x over previous
#include <cuda_runtime.h>
#include <cuda_fp16.h>
#include <math.h>
#include <stdint.h>

#define BB 64
#define TT 512
#define VV 256
#define MEM 1024
#define G4 4096

// ---------------- device scratch ----------------
__device__ float g_Zx[(size_t)TT * BB * G4];            // layer0 input-side z (+b0), gate-permuted cols, fp32
__device__ float g_hall[(size_t)TT * BB * MEM];         // h1 sequence fp32 (phase-5 input)
__device__ float g_c[2][BB * MEM];                      // cell state per layer, fp32
__device__ uint32_t g_h0[2][BB * 512];                  // h0 packed half2, double-buffered by round parity
__device__ uint32_t g_h1[2][BB * 512];                  // h1 packed half2
__device__ float g_hfin[2][BB * MEM];                   // final-step h, fp32
__device__ uint32_t g_W0h[((VV + MEM) / 2) * G4];       // W0 packed half2 pairs along k, gate-permuted cols
__device__ uint32_t g_W1h[((2 * MEM) / 2) * G4];        // W1 same
__device__ __half g_W0t[(size_t)G4 * (VV + MEM)];       // W0^T [n][k] halves, gate-permuted n (phase1 B)
__device__ __half g_W1t[(size_t)G4 * (2 * MEM)];        // W1^T [n][k] (streamed W1x source, u32 view)
__device__ __half g_Wot[(size_t)VV * MEM];              // W_out^T [n][k] halves
__device__ float g_b0p[G4];
__device__ float g_b1p[G4];
__device__ volatile int g_arrive[128];                  // grid-barrier flags

__device__ __forceinline__ float sigm(float x) { return 1.0f / (1.0f + expf(-x)); }
__device__ __forceinline__ uint32_t pk(float a, float b) {
    __half2 h = __floats2half2_rn(a, b);
    return *(uint32_t*)&h;
}
__device__ __forceinline__ uint32_t smem_u32(const void* p) {
    uint32_t a;
    asm("{ .reg .u64 t; cvta.to.shared.u64 t, %1; cvt.u32.u64 %0, t; }" : "=r"(a) : "l"(p));
    return a;
}
__device__ __forceinline__ void cpa16(uint32_t dst, const void* src) {
    asm volatile("cp.async.cg.shared.global [%0], [%1], 16;" :: "r"(dst), "l"(src));
}
__device__ __forceinline__ void cpa_commit() { asm volatile("cp.async.commit_group;" ::: "memory"); }
#define WAITG(n) asm volatile("cp.async.wait_group %0;" :: "n"(n) : "memory")

// m16n8k16 fp16 mma, fp32 accum
__device__ __forceinline__ void mma16(float* d, uint32_t a0, uint32_t a1, uint32_t a2, uint32_t a3,
                                      uint32_t b0, uint32_t b1) {
    asm volatile("mma.sync.aligned.m16n8k16.row.col.f32.f16.f16.f32 "
                 "{%0,%1,%2,%3}, {%4,%5,%6,%7}, {%8,%9}, {%0,%1,%2,%3};"
                 : "+f"(d[0]), "+f"(d[1]), "+f"(d[2]), "+f"(d[3])
                 : "r"(a0), "r"(a1), "r"(a2), "r"(a3), "r"(b0), "r"(b1));
}

// ---------------- init ----------------
__global__ void init_state(const float* __restrict__ s0, const float* __restrict__ s1) {
    int i = blockIdx.x * 256 + threadIdx.x;
    int b = i >> 10, u = i & 1023;
    g_c[0][i] = s0[b * 2 * MEM + u];
    g_c[1][i] = s1[b * 2 * MEM + u];
    if (u < 512) {
        int kp = u;
        g_h0[1][b * 512 + kp] = pk(s0[b * 2 * MEM + MEM + 2 * kp], s0[b * 2 * MEM + MEM + 2 * kp + 1]);
        g_h1[1][b * 512 + kp] = pk(s1[b * 2 * MEM + MEM + 2 * kp], s1[b * 2 * MEM + MEM + 2 * kp + 1]);
    }
    if (blockIdx.x == 0 && threadIdx.x < 128) g_arrive[threadIdx.x] = 0;
}

// ---------------- gate-permuted packed-half2 K-major weights + fp32 permuted biases ----------------
__global__ void permute_w(const float* __restrict__ W0, const float* __restrict__ b0,
                          const float* __restrict__ W1, const float* __restrict__ b1) {
    size_t i = (size_t)blockIdx.x * 256 + threadIdx.x;
    const size_t n0 = (size_t)((VV + MEM) / 2) * MEM;
    const size_t n1 = (size_t)((2 * MEM) / 2) * MEM;
    if (i < n0) {
        size_t kp = i >> 10; int u = (int)(i & 1023);
        const float* s = W0 + (size_t)(2 * kp) * G4 + u;
        uint4 v;
        v.x = pk(s[0],    s[G4]);
        v.y = pk(s[1024], s[G4 + 1024]);
        v.z = pk(s[2048], s[G4 + 2048]);
        v.w = pk(s[3072], s[G4 + 3072]);
        *(uint4*)&g_W0h[kp * G4 + (size_t)u * 4] = v;
    } else if (i < n0 + n1) {
        size_t k = i - n0;
        size_t kp = k >> 10; int u = (int)(k & 1023);
        const float* s = W1 + (size_t)(2 * kp) * G4 + u;
        uint4 v;
        v.x = pk(s[0],    s[G4]);
        v.y = pk(s[1024], s[G4 + 1024]);
        v.z = pk(s[2048], s[G4 + 2048]);
        v.w = pk(s[3072], s[G4 + 3072]);
        *(uint4*)&g_W1h[kp * G4 + (size_t)u * 4] = v;
    }
    if (i < MEM) {
        int u = (int)i;
        float4 vb0 = { b0[u], b0[1024 + u], b0[2048 + u], b0[3072 + u] };
        float4 vb1 = { b1[u], b1[1024 + u], b1[2048 + u], b1[3072 + u] };
        *(float4*)&g_b0p[u * 4] = vb0;
        *(float4*)&g_b1p[u * 4] = vb1;
    }
}

// ---------------- transposed half weights WT[n][k] (gate-permuted n) ----------------
__global__ __launch_bounds__(256) void transpose_w2(const float* __restrict__ W, int sel) {
    __shared__ float s[32][33];
    int tx = threadIdx.x & 31, ty = threadIdx.x >> 5;
    int k0 = blockIdx.x * 32, c0 = blockIdx.y * 32;
    __half* dst = (sel == 0) ? g_W0t : g_W1t;
    long wst = (sel == 0) ? (VV + MEM) : (2 * MEM);
#pragma unroll
    for (int j = 0; j < 4; j++)
        s[ty + j * 8][tx] = W[(size_t)(k0 + ty + j * 8) * G4 + c0 + tx];
    __syncthreads();
#pragma unroll
    for (int j = 0; j < 4; j++) {
        int c = c0 + ty + j * 8;
        int n = (c & 1023) * 4 + (c >> 10);
        dst[(size_t)n * wst + k0 + tx] = __float2half_rn(s[tx][ty + j * 8]);
    }
}

__global__ __launch_bounds__(256) void transpose_wout(const float* __restrict__ W) {
    __shared__ float s[32][33];
    int tx = threadIdx.x & 31, ty = threadIdx.x >> 5;
    int k0 = blockIdx.x * 32, c0 = blockIdx.y * 32;
#pragma unroll
    for (int j = 0; j < 4; j++)
        s[ty + j * 8][tx] = W[(size_t)(k0 + ty + j * 8) * VV + c0 + tx];
    __syncthreads();
#pragma unroll
    for (int j = 0; j < 4; j++) {
        int n = c0 + ty + j * 8;
        g_Wot[(size_t)n * MEM + k0 + tx] = __float2half_rn(s[tx][ty + j * 8]);
    }
}

// ---------------- fp16 mma GEMM (phases 1/5), unchanged ----------------
__global__ __launch_bounds__(256) void gemm_mma(
    const float* __restrict__ Ain, long sb, long st,
    long wst, int K, int src_gh, int w_sel,
    float* __restrict__ Cout, const float* __restrict__ bias_ext,
    long ocb, long oct)
{
    const float* A = src_gh ? (const float*)g_hall : Ain;
    const __half* WT = (w_sel == 0) ? g_W0t : ((w_sel == 1) ? g_W1t : g_Wot);
    const float* bias = (w_sel == 0) ? g_b0p : ((w_sel == 1) ? g_b1p : bias_ext);
    float* C = (w_sel == 2) ? Cout : (float*)g_Zx;

    __shared__ uint32_t As[128 * 32];
    __shared__ uint32_t Bs[64 * 32];

    const int tid = threadIdx.x;
    const int wid = tid >> 5, lane = tid & 31;
    const int gid = lane >> 2, tig = lane & 3;
    const int wm = wid & 3, wn = wid >> 2;
    const long brow = (long)blockIdx.y * 128;
    const int bcol = blockIdx.x * 64;

    int a_sw[4];
    const float* a_ptr[4];
#pragma unroll
    for (int i = 0; i < 4; i++) {
        int f = tid + i * 256;
        int row = f >> 3, g4 = f & 7;
        a_sw[i] = row * 32 + ((g4 * 4) ^ ((row & 7) * 4));
        long r = brow + row;
        a_ptr[i] = A + (r & 63) * sb + (r >> 6) * st + g4 * 8;
    }
    int b_sw[2];
    const uint32_t* b_ptr[2];
#pragma unroll
    for (int i = 0; i < 2; i++) {
        int f = tid + i * 256;
        int n = f >> 3, g4 = f & 7;
        b_sw[i] = n * 32 + ((g4 * 4) ^ ((n & 7) * 4));
        b_ptr[i] = (const uint32_t*)(WT + (size_t)(bcol + n) * wst) + g4 * 4;
    }

    float acc[2][4][4];
#pragma unroll
    for (int mt = 0; mt < 2; mt++)
#pragma unroll
        for (int nt = 0; nt < 4; nt++)
#pragma unroll
            for (int q = 0; q < 4; q++) acc[mt][nt][q] = 0.0f;

    const int arow0 = wm * 32 + gid;
    const int nb0 = wn * 32 + gid;
    const int xg = gid * 4;

    for (int kb = 0; kb < K; kb += 64) {
        float4 alo[4], ahi[4];
        uint4 bv[2];
#pragma unroll
        for (int i = 0; i < 4; i++) {
            alo[i] = *(const float4*)(a_ptr[i] + kb);
            ahi[i] = *(const float4*)(a_ptr[i] + kb + 4);
        }
#pragma unroll
        for (int i = 0; i < 2; i++) bv[i] = *(const uint4*)(b_ptr[i] + kb / 2);
        __syncthreads();
#pragma unroll
        for (int i = 0; i < 4; i++) {
            uint4 v;
            v.x = pk(alo[i].x, alo[i].y);
            v.y = pk(alo[i].z, alo[i].w);
            v.z = pk(ahi[i].x, ahi[i].y);
            v.w = pk(ahi[i].z, ahi[i].w);
            *(uint4*)&As[a_sw[i]] = v;
        }
#pragma unroll
        for (int i = 0; i < 2; i++) *(uint4*)&Bs[b_sw[i]] = bv[i];
        __syncthreads();

#pragma unroll
        for (int ks = 0; ks < 4; ks++) {
            int p0 = (ks * 8 + tig) ^ xg;
            int p1 = (ks * 8 + tig + 4) ^ xg;
            uint32_t a[2][4];
#pragma unroll
            for (int mt = 0; mt < 2; mt++) {
                int r0 = (arow0 + mt * 16) * 32;
                a[mt][0] = As[r0 + p0];
                a[mt][1] = As[r0 + 256 + p0];
                a[mt][2] = As[r0 + p1];
                a[mt][3] = As[r0 + 256 + p1];
            }
#pragma unroll
            for (int nt = 0; nt < 4; nt++) {
                int n = (nb0 + nt * 8) * 32;
                uint32_t b0 = Bs[n + p0];
                uint32_t b1 = Bs[n + p1];
#pragma unroll
                for (int mt = 0; mt < 2; mt++)
                    mma16(acc[mt][nt], a[mt][0], a[mt][1], a[mt][2], a[mt][3], b0, b1);
            }
        }
        __syncthreads();
    }

#pragma unroll
    for (int mt = 0; mt < 2; mt++) {
        long r2 = brow + wm * 32 + mt * 16 + gid;
        long co0 = (r2 & 63) * ocb + (r2 >> 6) * oct;
        long r3 = r2 + 8;
        long co1 = (r3 & 63) * ocb + (r3 >> 6) * oct;
#pragma unroll
        for (int nt = 0; nt < 4; nt++) {
            int col = bcol + wn * 32 + nt * 8 + tig * 2;
            float bz0 = bias[col], bz1 = bias[col + 1];
            float2 v0 = { acc[mt][nt][0] + bz0, acc[mt][nt][1] + bz1 };
            float2 v1 = { acc[mt][nt][2] + bz0, acc[mt][nt][3] + bz1 };
            *(float2*)(C + co0 + col) = v0;
            *(float2*)(C + co1 + col) = v1;
        }
    }
}

// ---------------- fused two-layer persistent recurrence: 513 rounds, 256 threads ----------------
// 16 units of 64-kp chunks (8 h0+W1x, 8 h1), 3 buffers, issue-after-sync; dual Zs, fused pointwise.
// smem: W0h [0,64K) | W1h [64K,128K) | Hb 3x16K [131072,180224) | Wb 3x8K [180224,204800)
//       | Zx 9216 [204800,214016). Zs0 [131072,+36864), Zs1 [167936,+36864) alias Hb+Wb.
#define SMB_W1   65536
#define SMB_HBUF 131072
#define SMB_WBUF 180224
#define SMB_ZX   204800
#define SMB_TOT2 214016

__global__ __launch_bounds__(256) void lstm_fused()
{
    extern __shared__ char dynraw[];
    uint32_t* W0_s = (uint32_t*)dynraw;                    // [32n][512kp^swz]
    uint32_t* W1_s = (uint32_t*)(dynraw + SMB_W1);
    uint32_t* Hb = (uint32_t*)(dynraw + SMB_HBUF);         // 3 x 4096 u32 ([64row][64col^swz])
    uint32_t* Wb = (uint32_t*)(dynraw + SMB_WBUF);         // 3 x 2048 u32 ([32n][64col^swz])
    float* Zs0 = (float*)(dynraw + SMB_HBUF);              // alias: [q4][64][36]
    float* Zs1 = (float*)(dynraw + SMB_HBUF + 36864);      // alias: [q4][64][36]
    float* Zx_s = (float*)(dynraw + SMB_ZX);               // [64][36]

    const int bid = blockIdx.x;
    const int tid = threadIdx.x;
    const int n0 = bid * 32;

    const int wid = tid >> 5, lane = tid & 31;
    const int gid = lane >> 2, tig = lane & 3;
    const int kq = wid & 3;        // k quarter (128 kp)
    const int wm = wid >> 2;       // m half (32 rows)
    const int xg = gid * 4;

    // preload resident W slices (h-parts), swizzled
    {
        const uint32_t* Wh0 = g_W0h + (size_t)(VV / 2) * G4;
        const uint32_t* Wh1 = g_W1h + (size_t)(MEM / 2) * G4;
        for (int idx = tid; idx < 32 * 512; idx += 256) {
            int kp = idx >> 5, n = idx & 31;
            int d = n * 512 + (kp ^ ((n & 7) * 4));
            W0_s[d] = Wh0[(size_t)kp * G4 + n0 + n];
            W1_s[d] = Wh1[(size_t)kp * G4 + n0 + n];
        }
    }

    const uint32_t sbase = smem_u32(dynraw);

    // h-chunk staging granules (i<4): g = i*256 + tid: q=g>>8, row=(g>>2)&63, k4=g&3
    // chunk u takes kp = q*128 + u*16 + k4*4.. (16 kp per quarter per chunk)
    uint32_t h_dst[4]; int h_soff[4];
#pragma unroll
    for (int i = 0; i < 4; i++) {
        int g = i * 256 + tid;
        int q = g >> 8, row = (g >> 2) & 63, k4 = g & 3;
        h_dst[i] = sbase + (uint32_t)SMB_HBUF
                 + (uint32_t)(row * 64 + ((q * 16 + k4 * 4) ^ ((row & 7) * 4))) * 4u;
        h_soff[i] = row * 512 + q * 128 + k4 * 4;   // + u*16 per chunk
    }
    // W1x chunk staging (i<2): g = i*256 + tid: n=g&31, q=(g>>5)&3, k4=(g>>7)&3
    uint32_t w_dst[2]; size_t w_soff[2];
#pragma unroll
    for (int i = 0; i < 2; i++) {
        int g = i * 256 + tid;
        int n = g & 31, q = (g >> 5) & 3, k4 = (g >> 7) & 3;
        w_dst[i] = sbase + (uint32_t)SMB_WBUF
                 + (uint32_t)(n * 64 + ((q * 16 + k4 * 4) ^ ((n & 7) * 4))) * 4u;
        w_soff[i] = (size_t)(n0 + n) * 1024 + q * 128 + k4 * 4;   // + u*16 per chunk
    }
    const uint32_t* w1x_src = (const uint32_t*)g_W1t;

    // Zx staging (i<2): g = tid + i*256: m=g>>3, c4=g&7
    uint32_t zx_dst[2]; int zx_soff[2];
#pragma unroll
    for (int i = 0; i < 2; i++) {
        int g = tid + i * 256;
        int m = g >> 3, c4 = g & 7;
        zx_dst[i] = sbase + (uint32_t)SMB_ZX + (uint32_t)(m * 36 + c4 * 4) * 4u;
        zx_soff[i] = m * G4 + n0 + c4 * 4;
    }

    // fragment constants (warp tile 32m x 32n, row stride 64 in chunk buffer)
    int a_base[2];
#pragma unroll
    for (int mt = 0; mt < 2; mt++)
        a_base[mt] = (wm * 32 + mt * 16 + gid) * 64;
    int b_nidx[4], bc_nidx[4];
#pragma unroll
    for (int nt = 0; nt < 4; nt++) {
        b_nidx[nt] = (nt * 8 + gid) * 512;    // resident W stride
        bc_nidx[nt] = (nt * 8 + gid) * 64;    // chunk W stride
    }

    // pointwise constants + c registers
    const int pm0 = tid >> 3, pj = tid & 7;
    const int ci0 = pm0 * MEM + bid * 8 + pj;
    const int ci1 = (pm0 + 32) * MEM + bid * 8 + pj;
    float c0a = g_c[0][ci0], c0b = g_c[0][ci1];
    float c1a = g_c[1][ci0], c1b = g_c[1][ci1];

    // Zx[0] prefetch
#pragma unroll
    for (int i = 0; i < 2; i++) cpa16(zx_dst[i], g_Zx + zx_soff[i]);
    cpa_commit();
    __syncthreads();   // resident W ready

    for (int r = 0; r <= TT; r++) {
        const int rp = r & 1;
        const uint32_t* h0r = g_h0[1 - rp];     // h0_{r-1}
        const uint32_t* h1r = g_h1[rp];         // h1_{r-2}
        __half* h0w = (__half*)g_h0[rp];
        __half* h1w = (__half*)g_h1[1 - rp];

        // unit u: u<8 -> h0 chunk u + W1x chunk u; u>=8 -> h1 chunk u-8
        auto issue = [&](int u) {
            uint32_t hb = (uint32_t)(u % 3) * 16384u;
            if (u < 8) {
#pragma unroll
                for (int i = 0; i < 4; i++) cpa16(h_dst[i] + hb, h0r + h_soff[i] + u * 16);
                uint32_t wb = (uint32_t)(u % 3) * 8192u;
#pragma unroll
                for (int i = 0; i < 2; i++) cpa16(w_dst[i] + wb, w1x_src + w_soff[i] + u * 16);
            } else {
                int j = u - 8;
#pragma unroll
                for (int i = 0; i < 4; i++) cpa16(h_dst[i] + hb, h1r + h_soff[i] + j * 16);
            }
        };

        issue(0); cpa_commit();
        issue(1); cpa_commit();

        float accL0[2][4][4], accL1[2][4][4];
#pragma unroll
        for (int mt = 0; mt < 2; mt++)
#pragma unroll
            for (int nt = 0; nt < 4; nt++)
#pragma unroll
                for (int q = 0; q < 4; q++) { accL0[mt][nt][q] = 0.0f; accL1[mt][nt][q] = 0.0f; }

        for (int u = 0; u < 16; u++) {
            if (u < 15) { WAITG(1); } else { WAITG(0); }
            __syncthreads();
            if (u < 14) { issue(u + 2); cpa_commit(); }

            const uint32_t* Ab = Hb + (u % 3) * 4096;
            if (u < 8) {
                const uint32_t* Wc = Wb + (u % 3) * 2048;
#pragma unroll
                for (int kk = 0; kk < 2; kk++) {
                    int x = kq * 16 + kk * 8 + tig;
                    int p0 = x ^ xg, p1 = (x + 4) ^ xg;
                    uint32_t a[2][4];
#pragma unroll
                    for (int mt = 0; mt < 2; mt++) {
                        a[mt][0] = Ab[a_base[mt] + p0];
                        a[mt][1] = Ab[a_base[mt] + 512 + p0];
                        a[mt][2] = Ab[a_base[mt] + p1];
                        a[mt][3] = Ab[a_base[mt] + 512 + p1];
                    }
                    int kp0 = kq * 128 + u * 16 + kk * 8 + tig;
#pragma unroll
                    for (int nt = 0; nt < 4; nt++) {
                        uint32_t b0 = W0_s[b_nidx[nt] + (kp0 ^ xg)];
                        uint32_t b1 = W0_s[b_nidx[nt] + ((kp0 + 4) ^ xg)];
                        uint32_t c0 = Wc[bc_nidx[nt] + p0];
                        uint32_t c1 = Wc[bc_nidx[nt] + p1];
#pragma unroll
                        for (int mt = 0; mt < 2; mt++) {
                            mma16(accL0[mt][nt], a[mt][0], a[mt][1], a[mt][2], a[mt][3], b0, b1);
                            mma16(accL1[mt][nt], a[mt][0], a[mt][1], a[mt][2], a[mt][3], c0, c1);
                        }
                    }
                }
            } else {
                int j = u - 8;
#pragma unroll
                for (int kk = 0; kk < 2; kk++) {
                    int x = kq * 16 + kk * 8 + tig;
                    int p0 = x ^ xg, p1 = (x + 4) ^ xg;
                    uint32_t a[2][4];
#pragma unroll
                    for (int mt = 0; mt < 2; mt++) {
                        a[mt][0] = Ab[a_base[mt] + p0];
                        a[mt][1] = Ab[a_base[mt] + 512 + p0];
                        a[mt][2] = Ab[a_base[mt] + p1];
                        a[mt][3] = Ab[a_base[mt] + 512 + p1];
                    }
                    int kp0 = kq * 128 + j * 16 + kk * 8 + tig;
#pragma unroll
                    for (int nt = 0; nt < 4; nt++) {
                        uint32_t b0 = W1_s[b_nidx[nt] + (kp0 ^ xg)];
                        uint32_t b1 = W1_s[b_nidx[nt] + ((kp0 + 4) ^ xg)];
#pragma unroll
                        for (int mt = 0; mt < 2; mt++)
                            mma16(accL1[mt][nt], a[mt][0], a[mt][1], a[mt][2], a[mt][3], b0, b1);
                    }
                }
            }
        }
        __syncthreads();   // all Hb/Wb reads done; Zs aliases now safe

        // ---- store split-K partials for BOTH layers, one sync ----
        if (r < TT) {
#pragma unroll
            for (int mt = 0; mt < 2; mt++) {
                int row = wm * 32 + mt * 16 + gid;
#pragma unroll
                for (int nt = 0; nt < 4; nt++) {
                    int col = nt * 8 + tig * 2;
                    *(float2*)&Zs0[kq * 2304 + row * 36 + col] =
                        make_float2(accL0[mt][nt][0], accL0[mt][nt][1]);
                    *(float2*)&Zs0[kq * 2304 + (row + 8) * 36 + col] =
                        make_float2(accL0[mt][nt][2], accL0[mt][nt][3]);
                }
            }
        }
        if (r >= 1) {
#pragma unroll
            for (int mt = 0; mt < 2; mt++) {
                int row = wm * 32 + mt * 16 + gid;
#pragma unroll
                for (int nt = 0; nt < 4; nt++) {
                    int col = nt * 8 + tig * 2;
                    *(float2*)&Zs1[kq * 2304 + row * 36 + col] =
                        make_float2(accL1[mt][nt][0], accL1[mt][nt][1]);
                    *(float2*)&Zs1[kq * 2304 + (row + 8) * 36 + col] =
                        make_float2(accL1[mt][nt][2], accL1[mt][nt][3]);
                }
            }
        }
        __syncthreads();

        // ---- fused pointwise: layer0 step r, layer1 step r-1 ----
        if (r < TT) {
#pragma unroll
            for (int e = 0; e < 2; e++) {
                int m = pm0 + e * 32;
                int ci = e ? ci1 : ci0;
                float4 z = *(const float4*)&Zx_s[m * 36 + pj * 4];
#pragma unroll
                for (int q = 0; q < 4; q++) {
                    float4 p = *(const float4*)&Zs0[q * 2304 + m * 36 + pj * 4];
                    z.x += p.x; z.y += p.y; z.z += p.z; z.w += p.w;
                }
                float c = e ? c0b : c0a;
                float cn = c * sigm(z.z + 1.0f) + sigm(z.x) * tanhf(z.y);
                float hn = tanhf(cn) * sigm(z.w);
                if (e) c0b = cn; else c0a = cn;
                h0w[m * MEM + bid * 8 + pj] = __float2half_rn(hn);
                if (r == TT - 1) g_hfin[0][ci] = hn;
            }
        }
        if (r >= 1) {
            const int t1 = r - 1;
            float4 bb = *(const float4*)&g_b1p[n0 + pj * 4];
#pragma unroll
            for (int e = 0; e < 2; e++) {
                int m = pm0 + e * 32;
                int ci = e ? ci1 : ci0;
                float4 z = bb;
#pragma unroll
                for (int q = 0; q < 4; q++) {
                    float4 p = *(const float4*)&Zs1[q * 2304 + m * 36 + pj * 4];
                    z.x += p.x; z.y += p.y; z.z += p.z; z.w += p.w;
                }
                float c = e ? c1b : c1a;
                float cn = c * sigm(z.z + 1.0f) + sigm(z.x) * tanhf(z.y);
                float hn = tanhf(cn) * sigm(z.w);
                if (e) c1b = cn; else c1a = cn;
                h1w[m * MEM + bid * 8 + pj] = __float2half_rn(hn);
                g_hall[(size_t)t1 * BB * MEM + ci] = hn;
                if (t1 == TT - 1) g_hfin[1][ci] = hn;
            }
        }

        // ---- publish + barrier ----
        if (r < TT) {
            __threadfence();
            __syncthreads();
            int want = r + 1;
            if (tid == 0) g_arrive[bid] = want;

            if (r + 1 < TT) {
                const float* zxn = g_Zx + (size_t)(r + 1) * BB * G4;
#pragma unroll
                for (int i = 0; i < 2; i++) cpa16(zx_dst[i], zxn + zx_soff[i]);
                cpa_commit();
            }

            if (tid < 128) {
                while (g_arrive[tid] < want) { }
            }
            __syncthreads();
        }
    }

    g_c[0][ci0] = c0a; g_c[0][ci1] = c0b;
    g_c[1][ci0] = c1a; g_c[1][ci1] = c1b;
}

// ---------------- pack final_state [2, B, 2*MEM] ----------------
__global__ void state_pack(float* __restrict__ out)
{
    int i = blockIdx.x * 256 + threadIdx.x;
    int l = i / (BB * 2 * MEM);
    int rem = i % (BB * 2 * MEM);
    int b = rem / (2 * MEM);
    int u = rem % (2 * MEM);
    out[i] = (u < MEM) ? g_c[l][b * MEM + u] : g_hfin[l][b * MEM + (u - MEM)];
}

extern "C" void kernel_launch(void* const* d_in, const int* in_sizes, int n_in,
                              void* d_out, int out_size)
{
    const float* x    = (const float*)d_in[0];
    const float* s0   = (const float*)d_in[1];
    const float* s1   = (const float*)d_in[2];
    const float* W0   = (const float*)d_in[3];
    const float* b0   = (const float*)d_in[4];
    const float* W1   = (const float*)d_in[5];
    const float* b1   = (const float*)d_in[6];
    const float* Wout = (const float*)d_in[7];
    const float* bout = (const float*)d_in[8];
    float* out = (float*)d_out;

    cudaFuncSetAttribute(lstm_fused,
                         cudaFuncAttributeMaxDynamicSharedMemorySize, SMB_TOT2);

    init_state<<<256, 256>>>(s0, s1);

    {
        size_t total = (size_t)((VV + MEM) / 2) * MEM + (size_t)MEM * MEM;
        int blocks = (int)((total + 255) / 256);
        permute_w<<<blocks, 256>>>(W0, b0, W1, b1);
    }
    transpose_w2<<<dim3((VV + MEM) / 32, G4 / 32), 256>>>(W0, 0);
    transpose_w2<<<dim3((2 * MEM) / 32, G4 / 32), 256>>>(W1, 1);
    transpose_wout<<<dim3(MEM / 32, VV / 32), 256>>>(Wout);

    // Phase 1: Zx = x @ W0[:256,:] + b0   (M=32768, N=4096, K=256)
    gemm_mma<<<dim3(64, 256), 256>>>(x, (long)TT * VV, (long)VV,
                                     (long)(VV + MEM), VV, 0, 0,
                                     nullptr, nullptr, (long)G4, (long)BB * G4);

    // Fused two-layer recurrence: 513 rounds, one launch, 256 threads/block
    lstm_fused<<<128, 256, SMB_TOT2>>>();

    // Phase 5: out[b,t,:] = h1_all @ W_out + b_out   (M=32768, N=256, K=1024)
    gemm_mma<<<dim3(4, 256), 256>>>(nullptr, (long)MEM, (long)BB * MEM,
                                    (long)MEM, MEM, 1, 2,
                                    out, bout, (long)TT * VV, (long)VV);

    state_pack<<<1024, 256>>>(out + (size_t)BB * TT * VV);
}